// round 3
// baseline (speedup 1.0000x reference)
#include <cuda_runtime.h>
#include <math.h>

// Problem dims (fixed by the reference)
#define BSZ   4
#define SEQ   2048
#define HD    1024
#define ED    2048
#define NST   16
#define RD    64
#define MROWS (BSZ * SEQ)   // 8192

// ---------------- scratch (static __device__, no allocs) ----------------
__device__ float g_xn[MROWS * HD];      // 32MB  layernorm output
__device__ float g_u[MROWS * ED];       // 64MB  silu(u)
__device__ float g_sg[MROWS * ED];      // 64MB  silu(gate)
__device__ float g_dtt[MROWS * RD];     // 2MB   u @ W_delta + b_delta
__device__ float g_delta[MROWS * ED];   // 64MB  softplus(...)
__device__ float g_Bm[MROWS * NST];     // 0.5MB
__device__ float g_Cm[MROWS * NST];     // 0.5MB
__device__ float g_y[MROWS * ED];       // 64MB  gated scan output

// ---------------- helpers ----------------
__device__ __forceinline__ float silu_f(float x) {
    return x / (1.0f + __expf(-x));
}
__device__ __forceinline__ float softplus_f(float x) {
    if (x > 0.0f)  return x + log1pf(expf(-x));
    else           return log1pf(expf(x));
}

// ---------------- LayerNorm: one block per row of 1024 ----------------
__global__ void ln_kernel(const float* __restrict__ x,
                          const float* __restrict__ g,
                          const float* __restrict__ b) {
    const int row = blockIdx.x;
    const int t   = threadIdx.x;          // 256 threads, 4 elems each
    const float4 v = reinterpret_cast<const float4*>(x + (size_t)row * HD)[t];

    float s = v.x + v.y + v.z + v.w;
    for (int o = 16; o; o >>= 1) s += __shfl_xor_sync(0xffffffffu, s, o);
    __shared__ float red[8];
    if ((t & 31) == 0) red[t >> 5] = s;
    __syncthreads();
    float tot = 0.f;
    if (t < 8) tot = red[t];
    if (t < 8) for (int o = 4; o; o >>= 1) tot += __shfl_xor_sync(0xffu, tot, o, 8);
    __shared__ float s_mu;
    if (t == 0) s_mu = tot / (float)HD;
    __syncthreads();
    const float mu = s_mu;

    float dx = v.x - mu, dy = v.y - mu, dz = v.z - mu, dw = v.w - mu;
    float sq = dx * dx + dy * dy + dz * dz + dw * dw;
    for (int o = 16; o; o >>= 1) sq += __shfl_xor_sync(0xffffffffu, sq, o);
    if ((t & 31) == 0) red[t >> 5] = sq;
    __syncthreads();
    float tot2 = 0.f;
    if (t < 8) tot2 = red[t];
    if (t < 8) for (int o = 4; o; o >>= 1) tot2 += __shfl_xor_sync(0xffu, tot2, o, 8);
    __shared__ float s_rs;
    if (t == 0) s_rs = rsqrtf(tot2 / (float)HD + 1e-5f);
    __syncthreads();
    const float rs = s_rs;

    const float4 gv = reinterpret_cast<const float4*>(g)[t];
    const float4 bv = reinterpret_cast<const float4*>(b)[t];
    float4 o4;
    o4.x = dx * rs * gv.x + bv.x;
    o4.y = dy * rs * gv.y + bv.y;
    o4.z = dz * rs * gv.z + bv.z;
    o4.w = dw * rs * gv.w + bv.w;
    reinterpret_cast<float4*>(g_xn + (size_t)row * HD)[t] = o4;
}

// ---------------- generic SGEMM 128x128x8, 256 threads, 8x8/thread ----------------
// C[M,N] = epi( A[M,K] @ B[K,N](ldb) + bias[N] (+ add[M,N]) )
#define EPI_NONE     0
#define EPI_SILU     1
#define EPI_SOFTPLUS 2

__global__ __launch_bounds__(256)
void sgemm_kernel(const float* __restrict__ A,
                  const float* __restrict__ Bw,
                  const float* __restrict__ bias,
                  const float* __restrict__ add,
                  float* __restrict__ C,
                  int M, int N, int K, int ldb, int ldc, int epi) {
    constexpr int BM = 128, BN = 128, BK = 8;
    __shared__ float As[BK][BM];
    __shared__ float Bs[BK][BN];

    const int t  = threadIdx.x;
    const int n0 = blockIdx.x * BN;
    const int m0 = blockIdx.y * BM;
    const int ty = t >> 4;        // 0..15
    const int tx = t & 15;        // 0..15

    const int ar = t >> 1;
    const int ac = (t & 1) * 4;
    const int br = t >> 5;
    const int bc = (t & 31) * 4;

    float acc[8][8];
#pragma unroll
    for (int i = 0; i < 8; i++)
#pragma unroll
        for (int j = 0; j < 8; j++) acc[i][j] = 0.f;

    for (int k0 = 0; k0 < K; k0 += BK) {
        float4 av = reinterpret_cast<const float4*>(A + (size_t)(m0 + ar) * K + k0 + ac)[0];
        As[ac + 0][ar] = av.x;
        As[ac + 1][ar] = av.y;
        As[ac + 2][ar] = av.z;
        As[ac + 3][ar] = av.w;
        float4 bv = make_float4(0.f, 0.f, 0.f, 0.f);
        if (n0 + bc < N)
            bv = reinterpret_cast<const float4*>(Bw + (size_t)(k0 + br) * ldb + n0 + bc)[0];
        reinterpret_cast<float4*>(&Bs[br][bc])[0] = bv;
        __syncthreads();

#pragma unroll
        for (int kk = 0; kk < BK; kk++) {
            float4 a0 = reinterpret_cast<float4*>(&As[kk][ty * 8])[0];
            float4 a1 = reinterpret_cast<float4*>(&As[kk][ty * 8])[1];
            float4 b0 = reinterpret_cast<float4*>(&Bs[kk][tx * 8])[0];
            float4 b1 = reinterpret_cast<float4*>(&Bs[kk][tx * 8])[1];
            float ra[8] = {a0.x, a0.y, a0.z, a0.w, a1.x, a1.y, a1.z, a1.w};
            float rb[8] = {b0.x, b0.y, b0.z, b0.w, b1.x, b1.y, b1.z, b1.w};
#pragma unroll
            for (int i = 0; i < 8; i++)
#pragma unroll
                for (int j = 0; j < 8; j++) acc[i][j] = fmaf(ra[i], rb[j], acc[i][j]);
        }
        __syncthreads();
    }

#pragma unroll
    for (int i = 0; i < 8; i++) {
        const int row = m0 + ty * 8 + i;
#pragma unroll
        for (int j = 0; j < 8; j++) {
            const int col = n0 + tx * 8 + j;
            if (col < N) {
                float v = acc[i][j] + bias[col];
                if (add) v += add[(size_t)row * ldc + col];
                if (epi == EPI_SILU)          v = silu_f(v);
                else if (epi == EPI_SOFTPLUS) v = softplus_f(v);
                C[(size_t)row * ldc + col] = v;
            }
        }
    }
}

// ---------------- fused B/C projection: one block per row ----------------
__global__ __launch_bounds__(256)
void bc_kernel(const float* __restrict__ W_B, const float* __restrict__ b_B,
               const float* __restrict__ W_C, const float* __restrict__ b_C) {
    const int row = blockIdx.x;
    const int t   = threadIdx.x;
    const int n   = t & 15;
    const int g   = t >> 4;                 // 0..15
    const float* ur = g_u + (size_t)row * ED;

    float accB = 0.f, accC = 0.f;
    for (int k = g; k < ED; k += 16) {
        const float uu = ur[k];
        accB = fmaf(uu, W_B[k * NST + n], accB);
        accC = fmaf(uu, W_C[k * NST + n], accC);
    }
    __shared__ float sB[256], sC[256];
    sB[t] = accB; sC[t] = accC;
    __syncthreads();
    for (int off = 128; off >= 16; off >>= 1) {
        if (t < off) { sB[t] += sB[t + off]; sC[t] += sC[t + off]; }
        __syncthreads();
    }
    if (t < 16) {
        g_Bm[(size_t)row * NST + t] = sB[t] + b_B[t];
        g_Cm[(size_t)row * NST + t] = sC[t] + b_C[t];
    }
}

// ---------------- selective scan ----------------
// 16 lanes per (b,e) group; lane n owns state n. Sequential over SEQ.
__global__ __launch_bounds__(256)
void scan_kernel(const float* __restrict__ A_log,
                 const float* __restrict__ D) {
    const int t    = threadIdx.x;
    const int pair = blockIdx.x * 16 + (t >> 4);   // (b,e) flat
    const int n    = t & 15;
    const int e    = pair & (ED - 1);
    const int b    = pair >> 11;                   // / ED

    const float a  = -expf(A_log[e * NST + n]);
    const float Dv = D[e];

    size_t base   = (size_t)(b * SEQ) * ED + e;
    size_t bcbase = (size_t)(b * SEQ) * NST + n;

    float h = 0.f;
    for (int s = 0; s < SEQ; s++) {
        const float d  = g_delta[base];
        const float uu = g_u[base];
        const float Bv = g_Bm[bcbase];
        const float Cv = g_Cm[bcbase];

        h = __expf(d * a) * h + d * Bv * uu;
        float p = Cv * h;
#pragma unroll
        for (int off = 8; off; off >>= 1)
            p += __shfl_xor_sync(0xffffffffu, p, off, 16);
        if (n == 0)
            g_y[base] = (p + uu * Dv) * g_sg[base];

        base   += ED;
        bcbase += NST;
    }
}

// ---------------- launch ----------------
extern "C" void kernel_launch(void* const* d_in, const int* in_sizes, int n_in,
                              void* d_out, int out_size) {
    const float* x       = (const float*)d_in[0];
    const float* ln_g    = (const float*)d_in[1];
    const float* ln_b    = (const float*)d_in[2];
    const float* W_in    = (const float*)d_in[3];
    const float* b_in    = (const float*)d_in[4];
    const float* W_delta = (const float*)d_in[5];
    const float* b_delta = (const float*)d_in[6];
    const float* W_dt    = (const float*)d_in[7];
    const float* b_dt    = (const float*)d_in[8];
    const float* W_B     = (const float*)d_in[9];
    const float* b_B     = (const float*)d_in[10];
    const float* W_C     = (const float*)d_in[11];
    const float* b_C     = (const float*)d_in[12];
    const float* A_log   = (const float*)d_in[13];
    const float* Dp      = (const float*)d_in[14];
    const float* W_out   = (const float*)d_in[15];
    const float* b_out   = (const float*)d_in[16];
    float* out = (float*)d_out;

    // device-symbol addresses resolved at compile time inside kernels; here we
    // only need them for sgemm arguments — use the fact that taking the
    // address of a __device__ variable in host code is invalid, so we pass
    // via small launcher-visible device pointers obtained through kernels
    // that reference the symbols directly. For sgemm we still need raw
    // pointers; use cudaGetSymbolAddress-free trick: declare device-side
    // constant pointers is overkill — simplest correct path: sgemm variants
    // take no scratch pointers for fixed operands. To keep one generic sgemm,
    // we resolve symbol addresses with cudaGetSymbolAddress, which is a
    // non-stream, non-allocating API and is legal outside capture too; BUT to
    // be maximally safe we do it with static locals? Not allowed (no caching).
    // => Just call it every time; it performs no device work and adds no
    // graph nodes.
    void *xn, *u, *sg, *dtt, *dlt, *yb;
    cudaGetSymbolAddress(&xn,  g_xn);
    cudaGetSymbolAddress(&u,   g_u);
    cudaGetSymbolAddress(&sg,  g_sg);
    cudaGetSymbolAddress(&dtt, g_dtt);
    cudaGetSymbolAddress(&dlt, g_delta);
    cudaGetSymbolAddress(&yb,  g_y);

    // 1. layernorm -> g_xn
    ln_kernel<<<MROWS, 256>>>(x, ln_g, ln_b);

    // 2. u = silu(xn @ W_in[:, :E]);  sg = silu(xn @ W_in[:, E:])
    sgemm_kernel<<<dim3(ED / 128, MROWS / 128), 256>>>(
        (const float*)xn, W_in,      b_in,      nullptr, (float*)u,
        MROWS, ED, HD, 2 * ED, ED, EPI_SILU);
    sgemm_kernel<<<dim3(ED / 128, MROWS / 128), 256>>>(
        (const float*)xn, W_in + ED, b_in + ED, nullptr, (float*)sg,
        MROWS, ED, HD, 2 * ED, ED, EPI_SILU);

    // 3. delta = softplus((u @ W_delta + b_delta) @ W_dt + b_dt)
    sgemm_kernel<<<dim3(1, MROWS / 128), 256>>>(
        (const float*)u,   W_delta, b_delta, nullptr, (float*)dtt,
        MROWS, RD, ED, RD, RD, EPI_NONE);
    sgemm_kernel<<<dim3(ED / 128, MROWS / 128), 256>>>(
        (const float*)dtt, W_dt,    b_dt,    nullptr, (float*)dlt,
        MROWS, ED, RD, ED, ED, EPI_SOFTPLUS);

    // 4. Bm, Cm (fused single pass over u)
    bc_kernel<<<MROWS, 256>>>(W_B, b_B, W_C, b_C);

    // 5. selective scan + (y + u*D) * silu(gate) fused -> g_y
    scan_kernel<<<(BSZ * ED) / 16, 256>>>(A_log, Dp);

    // 6. out = y @ W_out + b_out + resid(x)
    sgemm_kernel<<<dim3(HD / 128, MROWS / 128), 256>>>(
        (const float*)yb, W_out, b_out, x, out, MROWS, HD, ED, HD, HD, EPI_NONE);
}

// round 5
// speedup vs baseline: 1.7136x; 1.7136x over previous
#include <cuda_runtime.h>
#include <math.h>
#include <stdint.h>

// Problem dims (fixed by the reference)
#define BSZ   4
#define SEQ   2048
#define HD    1024
#define ED    2048
#define NST   16
#define RD    64
#define MROWS (BSZ * SEQ)   // 8192

// ---------------- scratch (static __device__, no allocs) ----------------
__device__ float g_xn[MROWS * HD];      // layernorm output
__device__ float g_u[MROWS * ED];       // silu(u)
__device__ float g_sg[MROWS * ED];      // silu(gate)
__device__ float g_dtt[MROWS * RD];     // u @ W_delta + b_delta
__device__ float g_delta[MROWS * ED];   // softplus(...)
__device__ float g_Bm[MROWS * NST];
__device__ float g_Cm[MROWS * NST];
__device__ float g_y[MROWS * ED];       // gated scan output

// ---------------- helpers ----------------
__device__ __forceinline__ float silu_f(float x) {
    return x / (1.0f + __expf(-x));
}
__device__ __forceinline__ float softplus_f(float x) {
    if (x > 0.0f)  return x + log1pf(expf(-x));
    else           return log1pf(expf(x));
}
__device__ __forceinline__ unsigned f2tf32(float f) {
    unsigned r;
    asm("cvt.rna.tf32.f32 %0, %1;" : "=r"(r) : "f"(f));
    return r;
}
__device__ __forceinline__ void mma_tf32(float* d, const unsigned* a,
                                         const unsigned* b, const float* c) {
    asm volatile(
        "mma.sync.aligned.m16n8k8.row.col.f32.tf32.tf32.f32 "
        "{%0,%1,%2,%3}, {%4,%5,%6,%7}, {%8,%9}, {%10,%11,%12,%13};\n"
        : "=f"(d[0]), "=f"(d[1]), "=f"(d[2]), "=f"(d[3])
        : "r"(a[0]), "r"(a[1]), "r"(a[2]), "r"(a[3]),
          "r"(b[0]), "r"(b[1]),
          "f"(c[0]), "f"(c[1]), "f"(c[2]), "f"(c[3]));
}

// ---------------- LayerNorm: one block per row of 1024 ----------------
__global__ void ln_kernel(const float* __restrict__ x,
                          const float* __restrict__ g,
                          const float* __restrict__ b) {
    const int row = blockIdx.x;
    const int t   = threadIdx.x;          // 256 threads, 4 elems each
    const float4 v = reinterpret_cast<const float4*>(x + (size_t)row * HD)[t];

    float s = v.x + v.y + v.z + v.w;
    for (int o = 16; o; o >>= 1) s += __shfl_xor_sync(0xffffffffu, s, o);
    __shared__ float red[8];
    if ((t & 31) == 0) red[t >> 5] = s;
    __syncthreads();
    float tot = 0.f;
    if (t < 8) tot = red[t];
    if (t < 8) for (int o = 4; o; o >>= 1) tot += __shfl_xor_sync(0xffu, tot, o, 8);
    __shared__ float s_mu;
    if (t == 0) s_mu = tot / (float)HD;
    __syncthreads();
    const float mu = s_mu;

    float dx = v.x - mu, dy = v.y - mu, dz = v.z - mu, dw = v.w - mu;
    float sq = dx * dx + dy * dy + dz * dz + dw * dw;
    for (int o = 16; o; o >>= 1) sq += __shfl_xor_sync(0xffffffffu, sq, o);
    if ((t & 31) == 0) red[t >> 5] = sq;
    __syncthreads();
    float tot2 = 0.f;
    if (t < 8) tot2 = red[t];
    if (t < 8) for (int o = 4; o; o >>= 1) tot2 += __shfl_xor_sync(0xffu, tot2, o, 8);
    __shared__ float s_rs;
    if (t == 0) s_rs = rsqrtf(tot2 / (float)HD + 1e-5f);
    __syncthreads();
    const float rs = s_rs;

    const float4 gv = reinterpret_cast<const float4*>(g)[t];
    const float4 bv = reinterpret_cast<const float4*>(b)[t];
    float4 o4;
    o4.x = dx * rs * gv.x + bv.x;
    o4.y = dy * rs * gv.y + bv.y;
    o4.z = dz * rs * gv.z + bv.z;
    o4.w = dw * rs * gv.w + bv.w;
    reinterpret_cast<float4*>(g_xn + (size_t)row * HD)[t] = o4;
}

// ---------------- TF32 tensor-core GEMM ----------------
// C[M,N] = epi( A[M,K] @ B[K,N] + bias[N] (+ add) )
// BM=128, BN=128, BK=16; 256 threads = 8 warps (4 M x 2 N), warp tile 32x64.
// Requires: M%128==0, N%128==0, K%16==0.
#define EPI_NONE     0
#define EPI_SILU     1
#define EPI_SOFTPLUS 2

template <int EPI, bool HAS_ADD>
__global__ __launch_bounds__(256)
void tf32_gemm(const float* __restrict__ A,
               const float* __restrict__ Bw,
               const float* __restrict__ bias,
               const float* __restrict__ add,
               float* __restrict__ C,
               int M, int N, int K, int lda, int ldb, int ldc) {
    __shared__ unsigned As[128][20];   // [m][k], pad 20: conflict-free frag loads
    __shared__ unsigned Bs[16][136];   // [k][n], pad 136: conflict-free frag loads

    const int t    = threadIdx.x;
    const int lane = t & 31;
    const int warp = t >> 5;
    const int qid  = lane >> 2;       // 0..7
    const int tq   = lane & 3;        // 0..3
    const int m_w  = (warp & 3) * 32;
    const int n_w  = (warp >> 2) * 64;
    const int m0   = blockIdx.y * 128;
    const int n0   = blockIdx.x * 128;

    float acc[2][8][4];
#pragma unroll
    for (int i = 0; i < 2; i++)
#pragma unroll
        for (int j = 0; j < 8; j++)
#pragma unroll
            for (int r = 0; r < 4; r++) acc[i][j][r] = 0.f;

    for (int k0 = 0; k0 < K; k0 += 16) {
        // stage A tile 128x16 (converted to tf32 bits)
#pragma unroll
        for (int p = 0; p < 2; p++) {
            const int idx = p * 256 + t;
            const int row = idx >> 2;
            const int c4  = (idx & 3) * 4;
            const float4 v = *reinterpret_cast<const float4*>(
                A + (size_t)(m0 + row) * lda + k0 + c4);
            As[row][c4 + 0] = f2tf32(v.x);
            As[row][c4 + 1] = f2tf32(v.y);
            As[row][c4 + 2] = f2tf32(v.z);
            As[row][c4 + 3] = f2tf32(v.w);
        }
        // stage B tile 16x128
#pragma unroll
        for (int p = 0; p < 2; p++) {
            const int idx = p * 256 + t;
            const int row = idx >> 5;
            const int c4  = (idx & 31) * 4;
            const float4 v = *reinterpret_cast<const float4*>(
                Bw + (size_t)(k0 + row) * ldb + n0 + c4);
            Bs[row][c4 + 0] = f2tf32(v.x);
            Bs[row][c4 + 1] = f2tf32(v.y);
            Bs[row][c4 + 2] = f2tf32(v.z);
            Bs[row][c4 + 3] = f2tf32(v.w);
        }
        __syncthreads();

#pragma unroll
        for (int k8 = 0; k8 < 16; k8 += 8) {
            unsigned af[2][4], bf[8][2];
#pragma unroll
            for (int i = 0; i < 2; i++) {
                const int mr = m_w + i * 16 + qid;
                af[i][0] = As[mr][k8 + tq];
                af[i][1] = As[mr + 8][k8 + tq];
                af[i][2] = As[mr][k8 + tq + 4];
                af[i][3] = As[mr + 8][k8 + tq + 4];
            }
#pragma unroll
            for (int j = 0; j < 8; j++) {
                const int nc = n_w + j * 8 + qid;
                bf[j][0] = Bs[k8 + tq][nc];
                bf[j][1] = Bs[k8 + tq + 4][nc];
            }
#pragma unroll
            for (int i = 0; i < 2; i++)
#pragma unroll
                for (int j = 0; j < 8; j++)
                    mma_tf32(acc[i][j], af[i], bf[j], acc[i][j]);
        }
        __syncthreads();
    }

    // epilogue
#pragma unroll
    for (int i = 0; i < 2; i++) {
        const int r0 = m0 + m_w + i * 16 + qid;
        const int r1 = r0 + 8;
#pragma unroll
        for (int j = 0; j < 8; j++) {
            const int c = n0 + n_w + j * 8 + 2 * tq;
            float v00 = acc[i][j][0] + bias[c];
            float v01 = acc[i][j][1] + bias[c + 1];
            float v10 = acc[i][j][2] + bias[c];
            float v11 = acc[i][j][3] + bias[c + 1];
            if (HAS_ADD) {
                v00 += add[(size_t)r0 * ldc + c];
                v01 += add[(size_t)r0 * ldc + c + 1];
                v10 += add[(size_t)r1 * ldc + c];
                v11 += add[(size_t)r1 * ldc + c + 1];
            }
            if (EPI == EPI_SILU) {
                v00 = silu_f(v00); v01 = silu_f(v01);
                v10 = silu_f(v10); v11 = silu_f(v11);
            } else if (EPI == EPI_SOFTPLUS) {
                v00 = softplus_f(v00); v01 = softplus_f(v01);
                v10 = softplus_f(v10); v11 = softplus_f(v11);
            }
            *reinterpret_cast<float2*>(C + (size_t)r0 * ldc + c) = make_float2(v00, v01);
            *reinterpret_cast<float2*>(C + (size_t)r1 * ldc + c) = make_float2(v10, v11);
        }
    }
}

// ---------------- scalar SGEMM 64x64 (for the N=64 dtt projection) ----------------
// grid (N/64, M/64); 256 threads, each 4x4.
__global__ __launch_bounds__(256)
void sgemm64_kernel(const float* __restrict__ A,
                    const float* __restrict__ Bw,
                    const float* __restrict__ bias,
                    float* __restrict__ C,
                    int M, int N, int K, int lda, int ldb, int ldc) {
    constexpr int BK = 16;
    __shared__ float As[BK][64 + 4];
    __shared__ float Bs[BK][64 + 4];

    const int t  = threadIdx.x;
    const int n0 = blockIdx.x * 64;
    const int m0 = blockIdx.y * 64;
    const int ty = t >> 4;
    const int tx = t & 15;

    const int ar = t >> 2;        // 0..63
    const int ac = (t & 3) * 4;   // 0,4,8,12
    const int br = t >> 4;        // 0..15
    const int bc = (t & 15) * 4;

    float acc[4][4];
#pragma unroll
    for (int i = 0; i < 4; i++)
#pragma unroll
        for (int j = 0; j < 4; j++) acc[i][j] = 0.f;

    for (int k0 = 0; k0 < K; k0 += BK) {
        float4 av = *reinterpret_cast<const float4*>(A + (size_t)(m0 + ar) * lda + k0 + ac);
        As[ac + 0][ar] = av.x; As[ac + 1][ar] = av.y;
        As[ac + 2][ar] = av.z; As[ac + 3][ar] = av.w;
        float4 bv = *reinterpret_cast<const float4*>(Bw + (size_t)(k0 + br) * ldb + n0 + bc);
        *reinterpret_cast<float4*>(&Bs[br][bc]) = bv;
        __syncthreads();

#pragma unroll
        for (int kk = 0; kk < BK; kk++) {
            float ra[4], rb[4];
#pragma unroll
            for (int i = 0; i < 4; i++) ra[i] = As[kk][ty * 4 + i];
#pragma unroll
            for (int j = 0; j < 4; j++) rb[j] = Bs[kk][tx * 4 + j];
#pragma unroll
            for (int i = 0; i < 4; i++)
#pragma unroll
                for (int j = 0; j < 4; j++) acc[i][j] = fmaf(ra[i], rb[j], acc[i][j]);
        }
        __syncthreads();
    }

#pragma unroll
    for (int i = 0; i < 4; i++) {
        const int row = m0 + ty * 4 + i;
#pragma unroll
        for (int j = 0; j < 4; j++) {
            const int col = n0 + tx * 4 + j;
            C[(size_t)row * ldc + col] = acc[i][j] + bias[col];
        }
    }
}

// ---------------- fused B/C projection: one block per row ----------------
__global__ __launch_bounds__(256)
void bc_kernel(const float* __restrict__ W_B, const float* __restrict__ b_B,
               const float* __restrict__ W_C, const float* __restrict__ b_C) {
    const int row = blockIdx.x;
    const int t   = threadIdx.x;
    const int n   = t & 15;
    const int g   = t >> 4;                 // 0..15
    const float* ur = g_u + (size_t)row * ED;

    float accB = 0.f, accC = 0.f;
    for (int k = g; k < ED; k += 16) {
        const float uu = ur[k];
        accB = fmaf(uu, W_B[k * NST + n], accB);
        accC = fmaf(uu, W_C[k * NST + n], accC);
    }
    __shared__ float sB[256], sC[256];
    sB[t] = accB; sC[t] = accC;
    __syncthreads();
    for (int off = 128; off >= 16; off >>= 1) {
        if (t < off) { sB[t] += sB[t + off]; sC[t] += sC[t + off]; }
        __syncthreads();
    }
    if (t < 16) {
        g_Bm[(size_t)row * NST + t] = sB[t] + b_B[t];
        g_Cm[(size_t)row * NST + t] = sC[t] + b_C[t];
    }
}

// ---------------- selective scan ----------------
// 16 lanes per (b,e) group; lane n owns state n. Sequential over SEQ.
__global__ __launch_bounds__(256)
void scan_kernel(const float* __restrict__ A_log,
                 const float* __restrict__ D) {
    const int t    = threadIdx.x;
    const int pair = blockIdx.x * 16 + (t >> 4);   // (b,e) flat
    const int n    = t & 15;
    const int e    = pair & (ED - 1);
    const int b    = pair >> 11;                   // / ED

    const float a  = -expf(A_log[e * NST + n]);
    const float Dv = D[e];

    size_t base   = (size_t)(b * SEQ) * ED + e;
    size_t bcbase = (size_t)(b * SEQ) * NST + n;

    float h = 0.f;
    for (int s = 0; s < SEQ; s++) {
        const float d  = g_delta[base];
        const float uu = g_u[base];
        const float Bv = g_Bm[bcbase];
        const float Cv = g_Cm[bcbase];

        h = __expf(d * a) * h + d * Bv * uu;
        float p = Cv * h;
#pragma unroll
        for (int off = 8; off; off >>= 1)
            p += __shfl_xor_sync(0xffffffffu, p, off, 16);
        if (n == 0)
            g_y[base] = (p + uu * Dv) * g_sg[base];

        base   += ED;
        bcbase += NST;
    }
}

// ---------------- launch ----------------
extern "C" void kernel_launch(void* const* d_in, const int* in_sizes, int n_in,
                              void* d_out, int out_size) {
    const float* x       = (const float*)d_in[0];
    const float* ln_g    = (const float*)d_in[1];
    const float* ln_b    = (const float*)d_in[2];
    const float* W_in    = (const float*)d_in[3];
    const float* b_in    = (const float*)d_in[4];
    const float* W_delta = (const float*)d_in[5];
    const float* b_delta = (const float*)d_in[6];
    const float* W_dt    = (const float*)d_in[7];
    const float* b_dt    = (const float*)d_in[8];
    const float* W_B     = (const float*)d_in[9];
    const float* b_B     = (const float*)d_in[10];
    const float* W_C     = (const float*)d_in[11];
    const float* b_C     = (const float*)d_in[12];
    const float* A_log   = (const float*)d_in[13];
    const float* Dp      = (const float*)d_in[14];
    const float* W_out   = (const float*)d_in[15];
    const float* b_out   = (const float*)d_in[16];
    float* out = (float*)d_out;

    void *xn, *u, *sg, *dtt, *dlt, *yb;
    cudaGetSymbolAddress(&xn,  g_xn);
    cudaGetSymbolAddress(&u,   g_u);
    cudaGetSymbolAddress(&sg,  g_sg);
    cudaGetSymbolAddress(&dtt, g_dtt);
    cudaGetSymbolAddress(&dlt, g_delta);
    cudaGetSymbolAddress(&yb,  g_y);

    // 1. layernorm -> g_xn
    ln_kernel<<<MROWS, 256>>>(x, ln_g, ln_b);

    // 2. u = silu(xn @ W_in[:, :E]);  sg = silu(xn @ W_in[:, E:])   (TF32)
    tf32_gemm<EPI_SILU, false><<<dim3(ED / 128, MROWS / 128), 256>>>(
        (const float*)xn, W_in,      b_in,      nullptr, (float*)u,
        MROWS, ED, HD, HD, 2 * ED, ED);
    tf32_gemm<EPI_SILU, false><<<dim3(ED / 128, MROWS / 128), 256>>>(
        (const float*)xn, W_in + ED, b_in + ED, nullptr, (float*)sg,
        MROWS, ED, HD, HD, 2 * ED, ED);

    // 3a. dtt = u @ W_delta + b_delta   (scalar, N=64, 128 CTAs)
    sgemm64_kernel<<<dim3(1, MROWS / 64), 256>>>(
        (const float*)u, W_delta, b_delta, (float*)dtt,
        MROWS, RD, ED, ED, RD, RD);
    // 3b. delta = softplus(dtt @ W_dt + b_dt)   (TF32, K=64)
    tf32_gemm<EPI_SOFTPLUS, false><<<dim3(ED / 128, MROWS / 128), 256>>>(
        (const float*)dtt, W_dt, b_dt, nullptr, (float*)dlt,
        MROWS, ED, RD, RD, ED, ED);

    // 4. Bm, Cm (fused single pass over u)
    bc_kernel<<<MROWS, 256>>>(W_B, b_B, W_C, b_C);

    // 5. selective scan + (y + u*D) * silu(gate) fused -> g_y
    scan_kernel<<<(BSZ * ED) / 16, 256>>>(A_log, Dp);

    // 6. out = y @ W_out + b_out + resid(x)   (TF32)
    tf32_gemm<EPI_NONE, true><<<dim3(HD / 128, MROWS / 128), 256>>>(
        (const float*)yb, W_out, b_out, x, out,
        MROWS, HD, ED, ED, HD, HD);
}

// round 6
// speedup vs baseline: 1.7298x; 1.0095x over previous
#include <cuda_runtime.h>
#include <math.h>
#include <stdint.h>

// Problem dims (fixed by the reference)
#define BSZ   4
#define SEQ   2048
#define HD    1024
#define ED    2048
#define NST   16
#define RD    64
#define MROWS (BSZ * SEQ)   // 8192

// ---------------- scratch (static __device__, no allocs) ----------------
__device__ float g_xn[MROWS * HD];      // layernorm output
__device__ float g_u[MROWS * ED];       // silu(u)
__device__ float g_sg[MROWS * ED];      // silu(gate)
__device__ float g_dtt[MROWS * RD];     // u @ W_delta + b_delta
__device__ float g_delta[MROWS * ED];   // softplus(...)
__device__ float g_Bm[MROWS * NST];
__device__ float g_Cm[MROWS * NST];
__device__ float g_y[MROWS * ED];       // gated scan output

// ---------------- helpers ----------------
__device__ __forceinline__ float silu_f(float x) {
    return x / (1.0f + __expf(-x));
}
__device__ __forceinline__ float softplus_f(float x) {
    if (x > 0.0f)  return x + log1pf(expf(-x));
    else           return log1pf(expf(x));
}
__device__ __forceinline__ void mma_tf32(float* d, const unsigned* a,
                                         const unsigned* b, const float* c) {
    asm volatile(
        "mma.sync.aligned.m16n8k8.row.col.f32.tf32.tf32.f32 "
        "{%0,%1,%2,%3}, {%4,%5,%6,%7}, {%8,%9}, {%10,%11,%12,%13};\n"
        : "=f"(d[0]), "=f"(d[1]), "=f"(d[2]), "=f"(d[3])
        : "r"(a[0]), "r"(a[1]), "r"(a[2]), "r"(a[3]),
          "r"(b[0]), "r"(b[1]),
          "f"(c[0]), "f"(c[1]), "f"(c[2]), "f"(c[3]));
}
__device__ __forceinline__ unsigned smem_u32(const void* p) {
    return (unsigned)__cvta_generic_to_shared(p);
}
#define CP_ASYNC16(saddr, gptr, sz) \
    asm volatile("cp.async.cg.shared.global [%0], [%1], 16, %2;" \
                 :: "r"(saddr), "l"(gptr), "r"(sz))
#define CP_COMMIT() asm volatile("cp.async.commit_group;")
#define CP_WAIT0()  asm volatile("cp.async.wait_group 0;")

// ---------------- LayerNorm: one block per row of 1024 ----------------
__global__ void ln_kernel(const float* __restrict__ x,
                          const float* __restrict__ g,
                          const float* __restrict__ b) {
    const int row = blockIdx.x;
    const int t   = threadIdx.x;          // 256 threads, 4 elems each
    const float4 v = reinterpret_cast<const float4*>(x + (size_t)row * HD)[t];

    float s = v.x + v.y + v.z + v.w;
    for (int o = 16; o; o >>= 1) s += __shfl_xor_sync(0xffffffffu, s, o);
    __shared__ float red[8];
    if ((t & 31) == 0) red[t >> 5] = s;
    __syncthreads();
    float tot = 0.f;
    if (t < 8) tot = red[t];
    if (t < 8) for (int o = 4; o; o >>= 1) tot += __shfl_xor_sync(0xffu, tot, o, 8);
    __shared__ float s_mu;
    if (t == 0) s_mu = tot / (float)HD;
    __syncthreads();
    const float mu = s_mu;

    float dx = v.x - mu, dy = v.y - mu, dz = v.z - mu, dw = v.w - mu;
    float sq = dx * dx + dy * dy + dz * dz + dw * dw;
    for (int o = 16; o; o >>= 1) sq += __shfl_xor_sync(0xffffffffu, sq, o);
    if ((t & 31) == 0) red[t >> 5] = sq;
    __syncthreads();
    float tot2 = 0.f;
    if (t < 8) tot2 = red[t];
    if (t < 8) for (int o = 4; o; o >>= 1) tot2 += __shfl_xor_sync(0xffu, tot2, o, 8);
    __shared__ float s_rs;
    if (t == 0) s_rs = rsqrtf(tot2 / (float)HD + 1e-5f);
    __syncthreads();
    const float rs = s_rs;

    const float4 gv = reinterpret_cast<const float4*>(g)[t];
    const float4 bv = reinterpret_cast<const float4*>(b)[t];
    float4 o4;
    o4.x = dx * rs * gv.x + bv.x;
    o4.y = dy * rs * gv.y + bv.y;
    o4.z = dz * rs * gv.z + bv.z;
    o4.w = dw * rs * gv.w + bv.w;
    reinterpret_cast<float4*>(g_xn + (size_t)row * HD)[t] = o4;
}

// ---------------- TF32 tensor-core GEMM, cp.async double-buffered ----------------
// C[M,N] = epi( A[M,K] @ B[K,N] + bias[N] (+ add) )
// BM=128, BN=128, BK=16; 256 threads = 8 warps (4 M x 2 N), warp tile 32x64.
// Requires: M%128==0, K%16==0. N may be < tile (zfill + store guards).
// Raw fp32 bits fed to tf32 mma (HW truncates mantissa).
#define EPI_NONE     0
#define EPI_SILU     1
#define EPI_SOFTPLUS 2

template <int EPI, bool HAS_ADD>
__global__ __launch_bounds__(256)
void tf32_gemm(const float* __restrict__ A,
               const float* __restrict__ Bw,
               const float* __restrict__ bias,
               const float* __restrict__ add,
               float* __restrict__ C,
               int M, int N, int K, int lda, int ldb, int ldc) {
    __shared__ unsigned As[2][128][20];   // [m][k], pad 20 -> conflict-free frags, 16B-mult pitch
    __shared__ unsigned Bs[2][16][136];   // [k][n], pad 136

    const int t    = threadIdx.x;
    const int lane = t & 31;
    const int warp = t >> 5;
    const int qid  = lane >> 2;       // 0..7
    const int tq   = lane & 3;        // 0..3
    const int m_w  = (warp & 3) * 32;
    const int n_w  = (warp >> 2) * 64;
    const int m0   = blockIdx.y * 128;
    const int n0   = blockIdx.x * 128;

    // staging maps
    const int ar = t >> 1;             // A row 0..127
    const int ac = (t & 1) * 8;        // A col 0 or 8  (two float4 per thread)
    const int br = t >> 4;             // B row 0..15
    const int bc = (t & 15) * 8;       // B col, two float4 per thread

    const float* gA = A + (size_t)(m0 + ar) * lda + ac;
    const float* gB = Bw + (size_t)br * ldb + n0 + bc;

    float acc[2][8][4];
#pragma unroll
    for (int i = 0; i < 2; i++)
#pragma unroll
        for (int j = 0; j < 8; j++)
#pragma unroll
            for (int r = 0; r < 4; r++) acc[i][j][r] = 0.f;

    const int T = K / 16;

    auto load_stage = [&](int buf, int kt) {
        const float* a = gA + kt * 16;
        unsigned sa = smem_u32(&As[buf][ar][ac]);
        CP_ASYNC16(sa,      a,     16);
        CP_ASYNC16(sa + 16, a + 4, 16);
        const float* b = gB + (size_t)kt * 16 * ldb;
        // zfill columns beyond N
        int ok0 = (n0 + bc     < N) ? 16 : 0;
        int ok1 = (n0 + bc + 4 < N) ? 16 : 0;
        const float* b0 = ok0 ? b     : Bw;
        const float* b1 = ok1 ? b + 4 : Bw;
        unsigned sb = smem_u32(&Bs[buf][br][bc]);
        CP_ASYNC16(sb,      b0, ok0);
        CP_ASYNC16(sb + 16, b1, ok1);
    };

    load_stage(0, 0);
    CP_COMMIT();

    for (int kt = 0; kt < T; kt++) {
        CP_WAIT0();
        __syncthreads();
        if (kt + 1 < T) load_stage((kt + 1) & 1, kt + 1);
        CP_COMMIT();

        const int buf = kt & 1;
#pragma unroll
        for (int k8 = 0; k8 < 16; k8 += 8) {
            unsigned af[2][4], bf[8][2];
#pragma unroll
            for (int i = 0; i < 2; i++) {
                const int mr = m_w + i * 16 + qid;
                af[i][0] = As[buf][mr][k8 + tq];
                af[i][1] = As[buf][mr + 8][k8 + tq];
                af[i][2] = As[buf][mr][k8 + tq + 4];
                af[i][3] = As[buf][mr + 8][k8 + tq + 4];
            }
#pragma unroll
            for (int j = 0; j < 8; j++) {
                const int nc = n_w + j * 8 + qid;
                bf[j][0] = Bs[buf][k8 + tq][nc];
                bf[j][1] = Bs[buf][k8 + tq + 4][nc];
            }
#pragma unroll
            for (int i = 0; i < 2; i++)
#pragma unroll
                for (int j = 0; j < 8; j++)
                    mma_tf32(acc[i][j], af[i], bf[j], acc[i][j]);
        }
    }

    // epilogue
#pragma unroll
    for (int i = 0; i < 2; i++) {
        const int r0 = m0 + m_w + i * 16 + qid;
        const int r1 = r0 + 8;
#pragma unroll
        for (int j = 0; j < 8; j++) {
            const int c = n0 + n_w + j * 8 + 2 * tq;
            if (c >= N) continue;
            const float bs0 = bias[c];
            const float bs1 = bias[c + 1];
            float v00 = acc[i][j][0] + bs0;
            float v01 = acc[i][j][1] + bs1;
            float v10 = acc[i][j][2] + bs0;
            float v11 = acc[i][j][3] + bs1;
            if (HAS_ADD) {
                v00 += add[(size_t)r0 * ldc + c];
                v01 += add[(size_t)r0 * ldc + c + 1];
                v10 += add[(size_t)r1 * ldc + c];
                v11 += add[(size_t)r1 * ldc + c + 1];
            }
            if (EPI == EPI_SILU) {
                v00 = silu_f(v00); v01 = silu_f(v01);
                v10 = silu_f(v10); v11 = silu_f(v11);
            } else if (EPI == EPI_SOFTPLUS) {
                v00 = softplus_f(v00); v01 = softplus_f(v01);
                v10 = softplus_f(v10); v11 = softplus_f(v11);
            }
            *reinterpret_cast<float2*>(C + (size_t)r0 * ldc + c) = make_float2(v00, v01);
            *reinterpret_cast<float2*>(C + (size_t)r1 * ldc + c) = make_float2(v10, v11);
        }
    }
}

// ---------------- fused B/C projection: one block per row ----------------
__global__ __launch_bounds__(256)
void bc_kernel(const float* __restrict__ W_B, const float* __restrict__ b_B,
               const float* __restrict__ W_C, const float* __restrict__ b_C) {
    const int row = blockIdx.x;
    const int t   = threadIdx.x;
    const int n   = t & 15;
    const int g   = t >> 4;                 // 0..15
    const float* ur = g_u + (size_t)row * ED;

    float accB = 0.f, accC = 0.f;
    for (int k = g; k < ED; k += 16) {
        const float uu = ur[k];
        accB = fmaf(uu, W_B[k * NST + n], accB);
        accC = fmaf(uu, W_C[k * NST + n], accC);
    }
    __shared__ float sB[256], sC[256];
    sB[t] = accB; sC[t] = accC;
    __syncthreads();
    for (int off = 128; off >= 16; off >>= 1) {
        if (t < off) { sB[t] += sB[t + off]; sC[t] += sC[t + off]; }
        __syncthreads();
    }
    if (t < 16) {
        g_Bm[(size_t)row * NST + t] = sB[t] + b_B[t];
        g_Cm[(size_t)row * NST + t] = sC[t] + b_C[t];
    }
}

// ---------------- selective scan ----------------
// 16 lanes per (b,e) group; lane n owns state n. Sequential over SEQ.
__global__ __launch_bounds__(256)
void scan_kernel(const float* __restrict__ A_log,
                 const float* __restrict__ D) {
    const int t    = threadIdx.x;
    const int pair = blockIdx.x * 16 + (t >> 4);   // (b,e) flat
    const int n    = t & 15;
    const int e    = pair & (ED - 1);
    const int b    = pair >> 11;                   // / ED

    const float a  = -expf(A_log[e * NST + n]);
    const float Dv = D[e];

    size_t base   = (size_t)(b * SEQ) * ED + e;
    size_t bcbase = (size_t)(b * SEQ) * NST + n;

    float h = 0.f;
    for (int s = 0; s < SEQ; s++) {
        const float d  = g_delta[base];
        const float uu = g_u[base];
        const float Bv = g_Bm[bcbase];
        const float Cv = g_Cm[bcbase];

        h = __expf(d * a) * h + d * Bv * uu;
        float p = Cv * h;
#pragma unroll
        for (int off = 8; off; off >>= 1)
            p += __shfl_xor_sync(0xffffffffu, p, off, 16);
        if (n == 0)
            g_y[base] = (p + uu * Dv) * g_sg[base];

        base   += ED;
        bcbase += NST;
    }
}

// ---------------- launch ----------------
extern "C" void kernel_launch(void* const* d_in, const int* in_sizes, int n_in,
                              void* d_out, int out_size) {
    const float* x       = (const float*)d_in[0];
    const float* ln_g    = (const float*)d_in[1];
    const float* ln_b    = (const float*)d_in[2];
    const float* W_in    = (const float*)d_in[3];
    const float* b_in    = (const float*)d_in[4];
    const float* W_delta = (const float*)d_in[5];
    const float* b_delta = (const float*)d_in[6];
    const float* W_dt    = (const float*)d_in[7];
    const float* b_dt    = (const float*)d_in[8];
    const float* W_B     = (const float*)d_in[9];
    const float* b_B     = (const float*)d_in[10];
    const float* W_C     = (const float*)d_in[11];
    const float* b_C     = (const float*)d_in[12];
    const float* A_log   = (const float*)d_in[13];
    const float* Dp      = (const float*)d_in[14];
    const float* W_out   = (const float*)d_in[15];
    const float* b_out   = (const float*)d_in[16];
    float* out = (float*)d_out;

    void *xn, *u, *sg, *dtt, *dlt, *yb;
    cudaGetSymbolAddress(&xn,  g_xn);
    cudaGetSymbolAddress(&u,   g_u);
    cudaGetSymbolAddress(&sg,  g_sg);
    cudaGetSymbolAddress(&dtt, g_dtt);
    cudaGetSymbolAddress(&dlt, g_delta);
    cudaGetSymbolAddress(&yb,  g_y);

    // 1. layernorm -> g_xn
    ln_kernel<<<MROWS, 256>>>(x, ln_g, ln_b);

    // 2. u = silu(xn @ W_in[:, :E]);  sg = silu(xn @ W_in[:, E:])   (TF32)
    tf32_gemm<EPI_SILU, false><<<dim3(ED / 128, MROWS / 128), 256>>>(
        (const float*)xn, W_in,      b_in,      nullptr, (float*)u,
        MROWS, ED, HD, HD, 2 * ED, ED);
    tf32_gemm<EPI_SILU, false><<<dim3(ED / 128, MROWS / 128), 256>>>(
        (const float*)xn, W_in + ED, b_in + ED, nullptr, (float*)sg,
        MROWS, ED, HD, HD, 2 * ED, ED);

    // 3a. dtt = u @ W_delta + b_delta   (TF32, N=64 via zfill + guards)
    tf32_gemm<EPI_NONE, false><<<dim3(1, MROWS / 128), 256>>>(
        (const float*)u, W_delta, b_delta, nullptr, (float*)dtt,
        MROWS, RD, ED, ED, RD, RD);
    // 3b. delta = softplus(dtt @ W_dt + b_dt)   (TF32, K=64)
    tf32_gemm<EPI_SOFTPLUS, false><<<dim3(ED / 128, MROWS / 128), 256>>>(
        (const float*)dtt, W_dt, b_dt, nullptr, (float*)dlt,
        MROWS, ED, RD, RD, ED, ED);

    // 4. Bm, Cm (fused single pass over u)
    bc_kernel<<<MROWS, 256>>>(W_B, b_B, W_C, b_C);

    // 5. selective scan + (y + u*D) * silu(gate) fused -> g_y
    scan_kernel<<<(BSZ * ED) / 16, 256>>>(A_log, Dp);

    // 6. out = y @ W_out + b_out + resid(x)   (TF32)
    tf32_gemm<EPI_NONE, true><<<dim3(HD / 128, MROWS / 128), 256>>>(
        (const float*)yb, W_out, b_out, x, out,
        MROWS, HD, ED, ED, HD, HD);
}

// round 7
// speedup vs baseline: 2.1248x; 1.2283x over previous
#include <cuda_runtime.h>
#include <math.h>
#include <stdint.h>

// Problem dims (fixed by the reference)
#define BSZ   4
#define SEQ   2048
#define HD    1024
#define ED    2048
#define NST   16
#define RD    64
#define MROWS (BSZ * SEQ)   // 8192

// ---------------- scratch (static __device__, no allocs) ----------------
__device__ float g_xn[MROWS * HD];        // layernorm output
__device__ float g_usg[MROWS * 2 * ED];   // [row][0..E) = silu(u), [row][E..2E) = silu(gate)
__device__ float g_dtt[MROWS * RD];       // u @ W_delta + b_delta
__device__ float g_delta[MROWS * ED];     // softplus(...)
__device__ float g_Bm[MROWS * NST];
__device__ float g_Cm[MROWS * NST];
__device__ float g_y[MROWS * ED];         // gated scan output

// ---------------- helpers ----------------
__device__ __forceinline__ float silu_f(float x) {
    return x / (1.0f + __expf(-x));
}
__device__ __forceinline__ float softplus_f(float x) {
    if (x > 0.0f)  return x + log1pf(expf(-x));
    else           return log1pf(expf(x));
}
__device__ __forceinline__ void mma_tf32(float* d, const unsigned* a,
                                         const unsigned* b, const float* c) {
    asm volatile(
        "mma.sync.aligned.m16n8k8.row.col.f32.tf32.tf32.f32 "
        "{%0,%1,%2,%3}, {%4,%5,%6,%7}, {%8,%9}, {%10,%11,%12,%13};\n"
        : "=f"(d[0]), "=f"(d[1]), "=f"(d[2]), "=f"(d[3])
        : "r"(a[0]), "r"(a[1]), "r"(a[2]), "r"(a[3]),
          "r"(b[0]), "r"(b[1]),
          "f"(c[0]), "f"(c[1]), "f"(c[2]), "f"(c[3]));
}
__device__ __forceinline__ unsigned smem_u32(const void* p) {
    return (unsigned)__cvta_generic_to_shared(p);
}
#define CP_ASYNC16(saddr, gptr, sz) \
    asm volatile("cp.async.cg.shared.global [%0], [%1], 16, %2;" \
                 :: "r"(saddr), "l"(gptr), "r"(sz))
#define CP_COMMIT() asm volatile("cp.async.commit_group;")
#define CP_WAIT0()  asm volatile("cp.async.wait_group 0;")

// ---------------- LayerNorm: one block per row of 1024 ----------------
__global__ void ln_kernel(const float* __restrict__ x,
                          const float* __restrict__ g,
                          const float* __restrict__ b) {
    const int row = blockIdx.x;
    const int t   = threadIdx.x;          // 256 threads, 4 elems each
    const float4 v = reinterpret_cast<const float4*>(x + (size_t)row * HD)[t];

    float s = v.x + v.y + v.z + v.w;
    for (int o = 16; o; o >>= 1) s += __shfl_xor_sync(0xffffffffu, s, o);
    __shared__ float red[8];
    if ((t & 31) == 0) red[t >> 5] = s;
    __syncthreads();
    float tot = 0.f;
    if (t < 8) tot = red[t];
    if (t < 8) for (int o = 4; o; o >>= 1) tot += __shfl_xor_sync(0xffu, tot, o, 8);
    __shared__ float s_mu;
    if (t == 0) s_mu = tot / (float)HD;
    __syncthreads();
    const float mu = s_mu;

    float dx = v.x - mu, dy = v.y - mu, dz = v.z - mu, dw = v.w - mu;
    float sq = dx * dx + dy * dy + dz * dz + dw * dw;
    for (int o = 16; o; o >>= 1) sq += __shfl_xor_sync(0xffffffffu, sq, o);
    if ((t & 31) == 0) red[t >> 5] = sq;
    __syncthreads();
    float tot2 = 0.f;
    if (t < 8) tot2 = red[t];
    if (t < 8) for (int o = 4; o; o >>= 1) tot2 += __shfl_xor_sync(0xffu, tot2, o, 8);
    __shared__ float s_rs;
    if (t == 0) s_rs = rsqrtf(tot2 / (float)HD + 1e-5f);
    __syncthreads();
    const float rs = s_rs;

    const float4 gv = reinterpret_cast<const float4*>(g)[t];
    const float4 bv = reinterpret_cast<const float4*>(b)[t];
    float4 o4;
    o4.x = dx * rs * gv.x + bv.x;
    o4.y = dy * rs * gv.y + bv.y;
    o4.z = dz * rs * gv.z + bv.z;
    o4.w = dw * rs * gv.w + bv.w;
    reinterpret_cast<float4*>(g_xn + (size_t)row * HD)[t] = o4;
}

// ---------------- TF32 tensor-core GEMM, cp.async double-buffered, 2 CTA/SM ----------------
// C[M,N] = epi( A[M,K] @ B[K,N] + bias[N] (+ add) )
// BM=128, BN=128, BK=16; 256 threads = 8 warps (4 M x 2 N), warp tile 32x64.
// Requires: M%128==0, K%16==0. N may be < tile (zfill + store guards).
#define EPI_NONE     0
#define EPI_SILU     1
#define EPI_SOFTPLUS 2

template <int EPI, bool HAS_ADD>
__global__ __launch_bounds__(256, 2)
void tf32_gemm(const float* __restrict__ A,
               const float* __restrict__ Bw,
               const float* __restrict__ bias,
               const float* __restrict__ add,
               float* __restrict__ C,
               int M, int N, int K, int lda, int ldb, int ldc) {
    __shared__ unsigned As[2][128][20];   // [m][k], pad 20 -> conflict-free frags
    __shared__ unsigned Bs[2][16][136];   // [k][n], pad 136

    const int t    = threadIdx.x;
    const int lane = t & 31;
    const int warp = t >> 5;
    const int qid  = lane >> 2;       // 0..7
    const int tq   = lane & 3;        // 0..3
    const int m_w  = (warp & 3) * 32;
    const int n_w  = (warp >> 2) * 64;
    const int m0   = blockIdx.y * 128;
    const int n0   = blockIdx.x * 128;

    // staging maps
    const int ar = t >> 1;             // A row 0..127
    const int ac = (t & 1) * 8;        // A col 0 or 8
    const int br = t >> 4;             // B row 0..15
    const int bc = (t & 15) * 8;       // B col

    const float* gA = A + (size_t)(m0 + ar) * lda + ac;
    const float* gB = Bw + (size_t)br * ldb + n0 + bc;

    float acc[2][8][4];
#pragma unroll
    for (int i = 0; i < 2; i++)
#pragma unroll
        for (int j = 0; j < 8; j++)
#pragma unroll
            for (int r = 0; r < 4; r++) acc[i][j][r] = 0.f;

    const int T = K / 16;

    auto load_stage = [&](int buf, int kt) {
        const float* a = gA + kt * 16;
        unsigned sa = smem_u32(&As[buf][ar][ac]);
        CP_ASYNC16(sa,      a,     16);
        CP_ASYNC16(sa + 16, a + 4, 16);
        const float* b = gB + (size_t)kt * 16 * ldb;
        int ok0 = (n0 + bc     < N) ? 16 : 0;   // zfill past N
        int ok1 = (n0 + bc + 4 < N) ? 16 : 0;
        const float* b0 = ok0 ? b     : Bw;
        const float* b1 = ok1 ? b + 4 : Bw;
        unsigned sb = smem_u32(&Bs[buf][br][bc]);
        CP_ASYNC16(sb,      b0, ok0);
        CP_ASYNC16(sb + 16, b1, ok1);
    };

    load_stage(0, 0);
    CP_COMMIT();

    for (int kt = 0; kt < T; kt++) {
        CP_WAIT0();
        __syncthreads();
        if (kt + 1 < T) load_stage((kt + 1) & 1, kt + 1);
        CP_COMMIT();

        const int buf = kt & 1;
#pragma unroll
        for (int k8 = 0; k8 < 16; k8 += 8) {
            unsigned af[2][4], bf[8][2];
#pragma unroll
            for (int i = 0; i < 2; i++) {
                const int mr = m_w + i * 16 + qid;
                af[i][0] = As[buf][mr][k8 + tq];
                af[i][1] = As[buf][mr + 8][k8 + tq];
                af[i][2] = As[buf][mr][k8 + tq + 4];
                af[i][3] = As[buf][mr + 8][k8 + tq + 4];
            }
#pragma unroll
            for (int j = 0; j < 8; j++) {
                const int nc = n_w + j * 8 + qid;
                bf[j][0] = Bs[buf][k8 + tq][nc];
                bf[j][1] = Bs[buf][k8 + tq + 4][nc];
            }
#pragma unroll
            for (int i = 0; i < 2; i++)
#pragma unroll
                for (int j = 0; j < 8; j++)
                    mma_tf32(acc[i][j], af[i], bf[j], acc[i][j]);
        }
    }

    // epilogue
#pragma unroll
    for (int i = 0; i < 2; i++) {
        const int r0 = m0 + m_w + i * 16 + qid;
        const int r1 = r0 + 8;
#pragma unroll
        for (int j = 0; j < 8; j++) {
            const int c = n0 + n_w + j * 8 + 2 * tq;
            if (c >= N) continue;
            const float bs0 = bias[c];
            const float bs1 = bias[c + 1];
            float v00 = acc[i][j][0] + bs0;
            float v01 = acc[i][j][1] + bs1;
            float v10 = acc[i][j][2] + bs0;
            float v11 = acc[i][j][3] + bs1;
            if (HAS_ADD) {
                v00 += add[(size_t)r0 * ldc + c];
                v01 += add[(size_t)r0 * ldc + c + 1];
                v10 += add[(size_t)r1 * ldc + c];
                v11 += add[(size_t)r1 * ldc + c + 1];
            }
            if (EPI == EPI_SILU) {
                v00 = silu_f(v00); v01 = silu_f(v01);
                v10 = silu_f(v10); v11 = silu_f(v11);
            } else if (EPI == EPI_SOFTPLUS) {
                v00 = softplus_f(v00); v01 = softplus_f(v01);
                v10 = softplus_f(v10); v11 = softplus_f(v11);
            }
            *reinterpret_cast<float2*>(C + (size_t)r0 * ldc + c) = make_float2(v00, v01);
            *reinterpret_cast<float2*>(C + (size_t)r1 * ldc + c) = make_float2(v10, v11);
        }
    }
}

// ---------------- fused B/C projection: one block per row ----------------
__global__ __launch_bounds__(256)
void bc_kernel(const float* __restrict__ W_B, const float* __restrict__ b_B,
               const float* __restrict__ W_C, const float* __restrict__ b_C) {
    const int row = blockIdx.x;
    const int t   = threadIdx.x;
    const int n   = t & 15;
    const int g   = t >> 4;                 // 0..15
    const float* ur = g_usg + (size_t)row * (2 * ED);   // u = cols [0, ED)

    float accB = 0.f, accC = 0.f;
    for (int k = g; k < ED; k += 16) {
        const float uu = ur[k];
        accB = fmaf(uu, W_B[k * NST + n], accB);
        accC = fmaf(uu, W_C[k * NST + n], accC);
    }
    __shared__ float sB[256], sC[256];
    sB[t] = accB; sC[t] = accC;
    __syncthreads();
    for (int off = 128; off >= 16; off >>= 1) {
        if (t < off) { sB[t] += sB[t + off]; sC[t] += sC[t + off]; }
        __syncthreads();
    }
    if (t < 16) {
        g_Bm[(size_t)row * NST + t] = sB[t] + b_B[t];
        g_Cm[(size_t)row * NST + t] = sC[t] + b_C[t];
    }
}

// ---------------- selective scan ----------------
// 16 lanes per (b,e) group; lane n owns state n. Sequential over SEQ.
__global__ __launch_bounds__(256)
void scan_kernel(const float* __restrict__ A_log,
                 const float* __restrict__ D) {
    const int t    = threadIdx.x;
    const int pair = blockIdx.x * 16 + (t >> 4);   // (b,e) flat
    const int n    = t & 15;
    const int e    = pair & (ED - 1);
    const int b    = pair >> 11;                   // / ED

    const float a  = -expf(A_log[e * NST + n]);
    const float Dv = D[e];

    size_t ubase  = (size_t)(b * SEQ) * (2 * ED) + e;   // u in g_usg, stride 2E
    size_t dbase  = (size_t)(b * SEQ) * ED + e;         // delta / y, stride E
    size_t bcbase = (size_t)(b * SEQ) * NST + n;

    float h = 0.f;
    for (int s = 0; s < SEQ; s++) {
        const float d  = g_delta[dbase];
        const float uu = g_usg[ubase];
        const float Bv = g_Bm[bcbase];
        const float Cv = g_Cm[bcbase];

        h = __expf(d * a) * h + d * Bv * uu;
        float p = Cv * h;
#pragma unroll
        for (int off = 8; off; off >>= 1)
            p += __shfl_xor_sync(0xffffffffu, p, off, 16);
        if (n == 0) {
            const float sgv = g_usg[ubase + ED];   // silu(gate), same row
            g_y[dbase] = (p + uu * Dv) * sgv;
        }

        ubase  += 2 * ED;
        dbase  += ED;
        bcbase += NST;
    }
}

// ---------------- launch ----------------
extern "C" void kernel_launch(void* const* d_in, const int* in_sizes, int n_in,
                              void* d_out, int out_size) {
    const float* x       = (const float*)d_in[0];
    const float* ln_g    = (const float*)d_in[1];
    const float* ln_b    = (const float*)d_in[2];
    const float* W_in    = (const float*)d_in[3];
    const float* b_in    = (const float*)d_in[4];
    const float* W_delta = (const float*)d_in[5];
    const float* b_delta = (const float*)d_in[6];
    const float* W_dt    = (const float*)d_in[7];
    const float* b_dt    = (const float*)d_in[8];
    const float* W_B     = (const float*)d_in[9];
    const float* b_B     = (const float*)d_in[10];
    const float* W_C     = (const float*)d_in[11];
    const float* b_C     = (const float*)d_in[12];
    const float* A_log   = (const float*)d_in[13];
    const float* Dp      = (const float*)d_in[14];
    const float* W_out   = (const float*)d_in[15];
    const float* b_out   = (const float*)d_in[16];
    float* out = (float*)d_out;

    void *xn, *usg, *dtt, *dlt, *yb;
    cudaGetSymbolAddress(&xn,  g_xn);
    cudaGetSymbolAddress(&usg, g_usg);
    cudaGetSymbolAddress(&dtt, g_dtt);
    cudaGetSymbolAddress(&dlt, g_delta);
    cudaGetSymbolAddress(&yb,  g_y);

    // 1. layernorm -> g_xn
    ln_kernel<<<MROWS, 256>>>(x, ln_g, ln_b);

    // 2. usg = silu(xn @ W_in + b_in)   (single N=4096 GEMM; u | sg packed)
    tf32_gemm<EPI_SILU, false><<<dim3(2 * ED / 128, MROWS / 128), 256>>>(
        (const float*)xn, W_in, b_in, nullptr, (float*)usg,
        MROWS, 2 * ED, HD, HD, 2 * ED, 2 * ED);

    // 3a. dtt = u @ W_delta + b_delta   (u = cols [0,E) of usg; lda = 2E)
    tf32_gemm<EPI_NONE, false><<<dim3(1, MROWS / 128), 256>>>(
        (const float*)usg, W_delta, b_delta, nullptr, (float*)dtt,
        MROWS, RD, ED, 2 * ED, RD, RD);
    // 3b. delta = softplus(dtt @ W_dt + b_dt)
    tf32_gemm<EPI_SOFTPLUS, false><<<dim3(ED / 128, MROWS / 128), 256>>>(
        (const float*)dtt, W_dt, b_dt, nullptr, (float*)dlt,
        MROWS, ED, RD, RD, ED, ED);

    // 4. Bm, Cm (fused single pass over u)
    bc_kernel<<<MROWS, 256>>>(W_B, b_B, W_C, b_C);

    // 5. selective scan + (y + u*D) * silu(gate) fused -> g_y
    scan_kernel<<<(BSZ * ED) / 16, 256>>>(A_log, Dp);

    // 6. out = y @ W_out + b_out + resid(x)
    tf32_gemm<EPI_NONE, true><<<dim3(HD / 128, MROWS / 128), 256>>>(
        (const float*)yb, W_out, b_out, x, out,
        MROWS, HD, ED, ED, HD, HD);
}

// round 9
// speedup vs baseline: 2.1730x; 1.0227x over previous
#include <cuda_runtime.h>
#include <math.h>
#include <stdint.h>

// Problem dims (fixed by the reference)
#define BSZ   4
#define SEQ   2048
#define HD    1024
#define ED    2048
#define NST   16
#define RD    64
#define MROWS (BSZ * SEQ)   // 8192

// ---------------- scratch (static __device__, no allocs) ----------------
__device__ float g_xn[MROWS * HD];        // layernorm output
__device__ float g_usg[MROWS * 2 * ED];   // [row][0..E)=silu(u), [row][E..2E)=silu(gate)
__device__ float g_dtt[MROWS * RD];
__device__ float g_delta[MROWS * ED];
__device__ float g_Bm[MROWS * NST];
__device__ float g_Cm[MROWS * NST];
__device__ float g_y[MROWS * ED];

// ---------------- helpers ----------------
__device__ __forceinline__ float silu_f(float x) {
    return x / (1.0f + __expf(-x));
}
__device__ __forceinline__ float softplus_f(float x) {
    if (x > 0.0f)  return x + log1pf(expf(-x));
    else           return log1pf(expf(x));
}
__device__ __forceinline__ void mma_tf32(float* d, const unsigned* a,
                                         const unsigned* b, const float* c) {
    asm volatile(
        "mma.sync.aligned.m16n8k8.row.col.f32.tf32.tf32.f32 "
        "{%0,%1,%2,%3}, {%4,%5,%6,%7}, {%8,%9}, {%10,%11,%12,%13};\n"
        : "=f"(d[0]), "=f"(d[1]), "=f"(d[2]), "=f"(d[3])
        : "r"(a[0]), "r"(a[1]), "r"(a[2]), "r"(a[3]),
          "r"(b[0]), "r"(b[1]),
          "f"(c[0]), "f"(c[1]), "f"(c[2]), "f"(c[3]));
}
__device__ __forceinline__ unsigned smem_u32(const void* p) {
    return (unsigned)__cvta_generic_to_shared(p);
}
#define CP_ASYNC16(saddr, gptr, sz) \
    asm volatile("cp.async.cg.shared.global [%0], [%1], 16, %2;" \
                 :: "r"(saddr), "l"(gptr), "r"(sz))
#define CP_COMMIT() asm volatile("cp.async.commit_group;")
#define CP_WAIT1()  asm volatile("cp.async.wait_group 1;")

// ---------------- LayerNorm: one block per row of 1024 ----------------
__global__ void ln_kernel(const float* __restrict__ x,
                          const float* __restrict__ g,
                          const float* __restrict__ b) {
    const int row = blockIdx.x;
    const int t   = threadIdx.x;          // 256 threads, 4 elems each
    const float4 v = reinterpret_cast<const float4*>(x + (size_t)row * HD)[t];

    float s = v.x + v.y + v.z + v.w;
    for (int o = 16; o; o >>= 1) s += __shfl_xor_sync(0xffffffffu, s, o);
    __shared__ float red[8];
    if ((t & 31) == 0) red[t >> 5] = s;
    __syncthreads();
    float tot = 0.f;
    if (t < 8) tot = red[t];
    if (t < 8) for (int o = 4; o; o >>= 1) tot += __shfl_xor_sync(0xffu, tot, o, 8);
    __shared__ float s_mu;
    if (t == 0) s_mu = tot / (float)HD;
    __syncthreads();
    const float mu = s_mu;

    float dx = v.x - mu, dy = v.y - mu, dz = v.z - mu, dw = v.w - mu;
    float sq = dx * dx + dy * dy + dz * dz + dw * dw;
    for (int o = 16; o; o >>= 1) sq += __shfl_xor_sync(0xffffffffu, sq, o);
    if ((t & 31) == 0) red[t >> 5] = sq;
    __syncthreads();
    float tot2 = 0.f;
    if (t < 8) tot2 = red[t];
    if (t < 8) for (int o = 4; o; o >>= 1) tot2 += __shfl_xor_sync(0xffu, tot2, o, 8);
    __shared__ float s_rs;
    if (t == 0) s_rs = rsqrtf(tot2 / (float)HD + 1e-5f);
    __syncthreads();
    const float rs = s_rs;

    const float4 gv = reinterpret_cast<const float4*>(g)[t];
    const float4 bv = reinterpret_cast<const float4*>(b)[t];
    float4 o4;
    o4.x = dx * rs * gv.x + bv.x;
    o4.y = dy * rs * gv.y + bv.y;
    o4.z = dz * rs * gv.z + bv.z;
    o4.w = dw * rs * gv.w + bv.w;
    reinterpret_cast<float4*>(g_xn + (size_t)row * HD)[t] = o4;
}

// ---------------- TF32 mma.sync GEMM, 3-stage cp.async ring, 2 CTA/SM ----------------
// C[M,N] = epi( A[M,K] @ B[K,N] + bias[N] (+ add) )
// BM=128, BN=128, BK=16; 256 threads = 8 warps (4 M x 2 N), warp tile 32x64.
// Requires: M%128==0, K%16==0. N may be < tile (zfill + store guards).
// Dynamic smem: 3 stages of As[128][20] + Bs[16][136] (unsigned words).
#define EPI_NONE     0
#define EPI_SILU     1
#define EPI_SOFTPLUS 2

#define AS_STRIDE  (128 * 20)          // words per A stage
#define BS_STRIDE  (16 * 136)          // words per B stage
#define AS_WORDS   (3 * AS_STRIDE)
#define GEMM_SMEM_BYTES ((AS_WORDS + 3 * BS_STRIDE) * 4)   // 56832

template <int EPI, bool HAS_ADD>
__global__ __launch_bounds__(256, 2)
void tf32_gemm(const float* __restrict__ A,
               const float* __restrict__ Bw,
               const float* __restrict__ bias,
               const float* __restrict__ add,
               float* __restrict__ C,
               int M, int N, int K, int lda, int ldb, int ldc) {
    extern __shared__ unsigned dsmem[];
    unsigned* AsBase = dsmem;                 // [3][128][20]
    unsigned* BsBase = dsmem + AS_WORDS;      // [3][16][136]

    const int t    = threadIdx.x;
    const int lane = t & 31;
    const int warp = t >> 5;
    const int qid  = lane >> 2;       // 0..7
    const int tq   = lane & 3;        // 0..3
    const int m_w  = (warp & 3) * 32;
    const int n_w  = (warp >> 2) * 64;
    const int m0   = blockIdx.y * 128;
    const int n0   = blockIdx.x * 128;

    // staging maps
    const int ar = t >> 1;             // A row 0..127
    const int ac = (t & 1) * 8;        // A col 0 or 8
    const int br = t >> 4;             // B row 0..15
    const int bc = (t & 15) * 8;       // B col

    const float* gA = A + (size_t)(m0 + ar) * lda + ac;
    const float* gB = Bw + (size_t)br * ldb + n0 + bc;

    float acc[2][8][4];
#pragma unroll
    for (int i = 0; i < 2; i++)
#pragma unroll
        for (int j = 0; j < 8; j++)
#pragma unroll
            for (int r = 0; r < 4; r++) acc[i][j][r] = 0.f;

    const int T = K / 16;

    auto load_stage = [&](int buf, int kt) {
        const float* a = gA + kt * 16;
        unsigned sa = smem_u32(AsBase + buf * AS_STRIDE + ar * 20 + ac);
        CP_ASYNC16(sa,      a,     16);
        CP_ASYNC16(sa + 16, a + 4, 16);
        const float* b = gB + (size_t)kt * 16 * ldb;
        int ok0 = (n0 + bc     < N) ? 16 : 0;   // zfill past N
        int ok1 = (n0 + bc + 4 < N) ? 16 : 0;
        const float* b0 = ok0 ? b     : Bw;
        const float* b1 = ok1 ? b + 4 : Bw;
        unsigned sb = smem_u32(BsBase + buf * BS_STRIDE + br * 136 + bc);
        CP_ASYNC16(sb,      b0, ok0);
        CP_ASYNC16(sb + 16, b1, ok1);
    };

    // prologue: stages 0 and 1 in flight (T >= 4 for all our shapes)
    load_stage(0, 0);
    CP_COMMIT();
    load_stage(1, 1);
    CP_COMMIT();

    int buf = 0;
    for (int kt = 0; kt < T; kt++) {
        CP_WAIT1();                 // tile kt's group complete (<=1 pending)
        __syncthreads();
        int buf2 = buf + 2; if (buf2 >= 3) buf2 -= 3;
        if (kt + 2 < T) load_stage(buf2, kt + 2);
        CP_COMMIT();                // commit (possibly empty) to keep counts uniform

        const unsigned* As = AsBase + buf * AS_STRIDE;
        const unsigned* Bs = BsBase + buf * BS_STRIDE;
#pragma unroll
        for (int k8 = 0; k8 < 16; k8 += 8) {
            unsigned af[2][4], bf[8][2];
#pragma unroll
            for (int i = 0; i < 2; i++) {
                const int mr = m_w + i * 16 + qid;
                af[i][0] = As[mr * 20 + k8 + tq];
                af[i][1] = As[(mr + 8) * 20 + k8 + tq];
                af[i][2] = As[mr * 20 + k8 + tq + 4];
                af[i][3] = As[(mr + 8) * 20 + k8 + tq + 4];
            }
#pragma unroll
            for (int j = 0; j < 8; j++) {
                const int nc = n_w + j * 8 + qid;
                bf[j][0] = Bs[(k8 + tq) * 136 + nc];
                bf[j][1] = Bs[(k8 + tq + 4) * 136 + nc];
            }
#pragma unroll
            for (int i = 0; i < 2; i++)
#pragma unroll
                for (int j = 0; j < 8; j++)
                    mma_tf32(acc[i][j], af[i], bf[j], acc[i][j]);
        }
        buf = buf + 1; if (buf >= 3) buf -= 3;
    }

    // epilogue
#pragma unroll
    for (int i = 0; i < 2; i++) {
        const int r0 = m0 + m_w + i * 16 + qid;
        const int r1 = r0 + 8;
#pragma unroll
        for (int j = 0; j < 8; j++) {
            const int c = n0 + n_w + j * 8 + 2 * tq;
            if (c >= N) continue;
            const float bs0 = bias[c];
            const float bs1 = bias[c + 1];
            float v00 = acc[i][j][0] + bs0;
            float v01 = acc[i][j][1] + bs1;
            float v10 = acc[i][j][2] + bs0;
            float v11 = acc[i][j][3] + bs1;
            if (HAS_ADD) {
                v00 += add[(size_t)r0 * ldc + c];
                v01 += add[(size_t)r0 * ldc + c + 1];
                v10 += add[(size_t)r1 * ldc + c];
                v11 += add[(size_t)r1 * ldc + c + 1];
            }
            if (EPI == EPI_SILU) {
                v00 = silu_f(v00); v01 = silu_f(v01);
                v10 = silu_f(v10); v11 = silu_f(v11);
            } else if (EPI == EPI_SOFTPLUS) {
                v00 = softplus_f(v00); v01 = softplus_f(v01);
                v10 = softplus_f(v10); v11 = softplus_f(v11);
            }
            *reinterpret_cast<float2*>(C + (size_t)r0 * ldc + c) = make_float2(v00, v01);
            *reinterpret_cast<float2*>(C + (size_t)r1 * ldc + c) = make_float2(v10, v11);
        }
    }
}

// ---------------- fused B/C projection: one block per row ----------------
__global__ __launch_bounds__(256)
void bc_kernel(const float* __restrict__ W_B, const float* __restrict__ b_B,
               const float* __restrict__ W_C, const float* __restrict__ b_C) {
    const int row = blockIdx.x;
    const int t   = threadIdx.x;
    const int n   = t & 15;
    const int g   = t >> 4;                 // 0..15
    const float* ur = g_usg + (size_t)row * (2 * ED);   // u = cols [0, ED)

    float accB = 0.f, accC = 0.f;
    for (int k = g; k < ED; k += 16) {
        const float uu = ur[k];
        accB = fmaf(uu, W_B[k * NST + n], accB);
        accC = fmaf(uu, W_C[k * NST + n], accC);
    }
    __shared__ float sB[256], sC[256];
    sB[t] = accB; sC[t] = accC;
    __syncthreads();
    for (int off = 128; off >= 16; off >>= 1) {
        if (t < off) { sB[t] += sB[t + off]; sC[t] += sC[t + off]; }
        __syncthreads();
    }
    if (t < 16) {
        g_Bm[(size_t)row * NST + t] = sB[t] + b_B[t];
        g_Cm[(size_t)row * NST + t] = sC[t] + b_C[t];
    }
}

// ---------------- selective scan ----------------
// 16 lanes per (b,e) group; lane n owns state n. Sequential over SEQ.
__global__ __launch_bounds__(256)
void scan_kernel(const float* __restrict__ A_log,
                 const float* __restrict__ D) {
    const int t    = threadIdx.x;
    const int pair = blockIdx.x * 16 + (t >> 4);   // (b,e) flat
    const int n    = t & 15;
    const int e    = pair & (ED - 1);
    const int b    = pair >> 11;                   // / ED

    const float a  = -expf(A_log[e * NST + n]);
    const float Dv = D[e];

    size_t ubase  = (size_t)(b * SEQ) * (2 * ED) + e;   // u in g_usg, stride 2E
    size_t dbase  = (size_t)(b * SEQ) * ED + e;         // delta / y, stride E
    size_t bcbase = (size_t)(b * SEQ) * NST + n;

    float h = 0.f;
    for (int s = 0; s < SEQ; s++) {
        const float d  = g_delta[dbase];
        const float uu = g_usg[ubase];
        const float Bv = g_Bm[bcbase];
        const float Cv = g_Cm[bcbase];

        h = __expf(d * a) * h + d * Bv * uu;
        float p = Cv * h;
#pragma unroll
        for (int off = 8; off; off >>= 1)
            p += __shfl_xor_sync(0xffffffffu, p, off, 16);
        if (n == 0) {
            const float sgv = g_usg[ubase + ED];   // silu(gate), same row
            g_y[dbase] = (p + uu * Dv) * sgv;
        }

        ubase  += 2 * ED;
        dbase  += ED;
        bcbase += NST;
    }
}

// ---------------- launch ----------------
extern "C" void kernel_launch(void* const* d_in, const int* in_sizes, int n_in,
                              void* d_out, int out_size) {
    const float* x       = (const float*)d_in[0];
    const float* ln_g    = (const float*)d_in[1];
    const float* ln_b    = (const float*)d_in[2];
    const float* W_in    = (const float*)d_in[3];
    const float* b_in    = (const float*)d_in[4];
    const float* W_delta = (const float*)d_in[5];
    const float* b_delta = (const float*)d_in[6];
    const float* W_dt    = (const float*)d_in[7];
    const float* b_dt    = (const float*)d_in[8];
    const float* W_B     = (const float*)d_in[9];
    const float* b_B     = (const float*)d_in[10];
    const float* W_C     = (const float*)d_in[11];
    const float* b_C     = (const float*)d_in[12];
    const float* A_log   = (const float*)d_in[13];
    const float* Dp      = (const float*)d_in[14];
    const float* W_out   = (const float*)d_in[15];
    const float* b_out   = (const float*)d_in[16];
    float* out = (float*)d_out;

    void *xn, *usg, *dtt, *dlt, *yb;
    cudaGetSymbolAddress(&xn,  g_xn);
    cudaGetSymbolAddress(&usg, g_usg);
    cudaGetSymbolAddress(&dtt, g_dtt);
    cudaGetSymbolAddress(&dlt, g_delta);
    cudaGetSymbolAddress(&yb,  g_y);

    // opt-in to >48KB dynamic smem for each instantiation (non-stream API;
    // idempotent, capture-safe)
    cudaFuncSetAttribute(tf32_gemm<EPI_SILU, false>,
                         cudaFuncAttributeMaxDynamicSharedMemorySize, GEMM_SMEM_BYTES);
    cudaFuncSetAttribute(tf32_gemm<EPI_NONE, false>,
                         cudaFuncAttributeMaxDynamicSharedMemorySize, GEMM_SMEM_BYTES);
    cudaFuncSetAttribute(tf32_gemm<EPI_SOFTPLUS, false>,
                         cudaFuncAttributeMaxDynamicSharedMemorySize, GEMM_SMEM_BYTES);
    cudaFuncSetAttribute(tf32_gemm<EPI_NONE, true>,
                         cudaFuncAttributeMaxDynamicSharedMemorySize, GEMM_SMEM_BYTES);

    // 1. layernorm -> g_xn
    ln_kernel<<<MROWS, 256>>>(x, ln_g, ln_b);

    // 2. usg = silu(xn @ W_in + b_in)   (single N=4096 GEMM; u | sg packed)
    tf32_gemm<EPI_SILU, false><<<dim3(2 * ED / 128, MROWS / 128), 256, GEMM_SMEM_BYTES>>>(
        (const float*)xn, W_in, b_in, nullptr, (float*)usg,
        MROWS, 2 * ED, HD, HD, 2 * ED, 2 * ED);

    // 3a. dtt = u @ W_delta + b_delta   (u = cols [0,E) of usg; lda = 2E)
    tf32_gemm<EPI_NONE, false><<<dim3(1, MROWS / 128), 256, GEMM_SMEM_BYTES>>>(
        (const float*)usg, W_delta, b_delta, nullptr, (float*)dtt,
        MROWS, RD, ED, 2 * ED, RD, RD);
    // 3b. delta = softplus(dtt @ W_dt + b_dt)
    tf32_gemm<EPI_SOFTPLUS, false><<<dim3(ED / 128, MROWS / 128), 256, GEMM_SMEM_BYTES>>>(
        (const float*)dtt, W_dt, b_dt, nullptr, (float*)dlt,
        MROWS, ED, RD, RD, ED, ED);

    // 4. Bm, Cm (fused single pass over u)
    bc_kernel<<<MROWS, 256>>>(W_B, b_B, W_C, b_C);

    // 5. selective scan + (y + u*D) * silu(gate) fused -> g_y
    scan_kernel<<<(BSZ * ED) / 16, 256>>>(A_log, Dp);

    // 6. out = y @ W_out + b_out + resid(x)
    tf32_gemm<EPI_NONE, true><<<dim3(HD / 128, MROWS / 128), 256, GEMM_SMEM_BYTES>>>(
        (const float*)yb, W_out, b_out, x, out,
        MROWS, HD, ED, ED, HD, HD);
}